// round 7
// baseline (speedup 1.0000x reference)
#include <cuda_runtime.h>
#include <cuda_bf16.h>
#include <cstdint>

// Problem constants (fixed by the reference)
#define T_ 4096
#define B_ 8
#define F_ 512
#define H_ 1024

#define X_ELEMS (T_ * B_ * F_)    // 16,777,216
#define W_ELEMS (B_ * F_ * H_)    //  4,194,304

// bf16 hi/lo scratch (static device globals: the legal scratch mechanism)
// x kept [T,B,F] (k contiguous); w transposed to [B,H,F] (k contiguous)
__device__ uint16_t g_xh[X_ELEMS];
__device__ uint16_t g_xl[X_ELEMS];
__device__ uint16_t g_whT[W_ELEMS];
__device__ uint16_t g_wlT[W_ELEMS];

// ---------------------------------------------------------------------------
// helpers
// ---------------------------------------------------------------------------
__device__ __forceinline__ float fix_nan(float v) {
    unsigned u = __float_as_uint(v) & 0x7fffffffu;
    return (u > 0x7f800000u) ? 0.0f : v;
}
__device__ __forceinline__ float bfr(float v) {
    return __bfloat162float(__float2bfloat16(v));
}
__device__ __forceinline__ uint32_t f2bf2(float lo, float hi) {
    uint32_t r;
    asm("cvt.rn.bf16x2.f32 %0, %1, %2;" : "=r"(r) : "f"(hi), "f"(lo));
    return r;
}
__device__ __forceinline__ uint16_t f2bf1(float v) {
    __nv_bfloat16 h = __float2bfloat16(v);
    return *reinterpret_cast<uint16_t*>(&h);
}
__device__ __forceinline__ uint32_t smem_u32(const void* p) {
    uint32_t r;
    asm("{ .reg .u64 t; cvta.to.shared.u64 t, %1; cvt.u32.u64 %0, t; }" : "=r"(r) : "l"(p));
    return r;
}
__device__ __forceinline__ void cp16(uint32_t dst, const void* src) {
    asm volatile("cp.async.cg.shared.global [%0], [%1], 16;" :: "r"(dst), "l"(src) : "memory");
}
__device__ __forceinline__ void ldsm4(uint32_t r[4], uint32_t addr) {
    asm volatile("ldmatrix.sync.aligned.m8n8.x4.shared.b16 {%0,%1,%2,%3}, [%4];"
                 : "=r"(r[0]), "=r"(r[1]), "=r"(r[2]), "=r"(r[3]) : "r"(addr));
}
__device__ __forceinline__ void mma_bf16(float c[4],
                                         uint32_t a0, uint32_t a1, uint32_t a2, uint32_t a3,
                                         uint32_t b0, uint32_t b1) {
    asm volatile("mma.sync.aligned.m16n8k16.row.col.f32.bf16.bf16.f32 "
                 "{%0,%1,%2,%3}, {%4,%5,%6,%7}, {%8,%9}, {%0,%1,%2,%3};"
                 : "+f"(c[0]), "+f"(c[1]), "+f"(c[2]), "+f"(c[3])
                 : "r"(a0), "r"(a1), "r"(a2), "r"(a3), "r"(b0), "r"(b1));
}

// ---------------------------------------------------------------------------
// Pre-conversion kernels
// ---------------------------------------------------------------------------
__global__ void __launch_bounds__(256)
convert_x_kernel(const float* __restrict__ x)
{
    const size_t i = ((size_t)blockIdx.x * 256 + threadIdx.x) * 4;
    float4 v = *(const float4*)(x + i);
    float a = fix_nan(v.x), bb = fix_nan(v.y), c = fix_nan(v.z), d = fix_nan(v.w);
    float ha = bfr(a), hb = bfr(bb), hc = bfr(c), hd = bfr(d);
    *(uint2*)(g_xh + i) = make_uint2(f2bf2(ha, hb), f2bf2(hc, hd));
    *(uint2*)(g_xl + i) = make_uint2(f2bf2(a - ha, bb - hb), f2bf2(c - hc, d - hd));
}

// transpose w1 [B][F][H] -> [B][H][F], split into bf16 hi/lo
__global__ void __launch_bounds__(256)
convert_wT_kernel(const float* __restrict__ w1)
{
    __shared__ float tile[32][33];
    const int k0 = blockIdx.x * 32;
    const int n0 = blockIdx.y * 32;
    const int b  = blockIdx.z;
    const int tx = threadIdx.x & 31;
    const int ty = threadIdx.x >> 5;   // 0..7

#pragma unroll
    for (int r = 0; r < 4; ++r) {
        const int k = ty + 8 * r;
        tile[k][tx] = w1[((size_t)b * F_ + (k0 + k)) * H_ + n0 + tx];
    }
    __syncthreads();
#pragma unroll
    for (int r = 0; r < 4; ++r) {
        const int n = ty + 8 * r;
        const float v = tile[tx][n];          // out[n][k=tx] = in[k=tx][n]
        const float h = bfr(v);
        const size_t o = ((size_t)b * H_ + (n0 + n)) * F_ + k0 + tx;
        g_whT[o] = f2bf1(h);
        g_wlT[o] = f2bf1(v - h);
    }
}

// ---------------------------------------------------------------------------
// mma.sync GEMM, cp.async 3-stage pipeline, TK=32, flat (hc,kt) loop
// Stage layout (32 KB): Ah[128x64B] Al[...] Bh[128x64B] Bl[...]
// 64B rows, XOR-swizzled 16B chunks: phys_chunk = c ^ ((row>>1)&3)
// ---------------------------------------------------------------------------
#define STAGE_BYTES 32768
#define OFF_AH 0
#define OFF_AL 8192
#define OFF_BH 16384
#define OFF_BL 24576
#define DYN_BYTES (3 * STAGE_BYTES)

__global__ void __launch_bounds__(256, 2)
mothernet_mma2(const float* __restrict__ b1,   // [B, H]
               const float* __restrict__ w2,   // [B, H]
               const float* __restrict__ b2,   // [B]
               float* __restrict__ out)        // [T, B]
{
    extern __shared__ __align__(128) uint8_t dynraw[];
    __shared__ float red[128 * 4];

    const uint32_t dyn = smem_u32(dynraw);

    const int b    = blockIdx.y;
    const int t0   = blockIdx.x * 128;
    const int tid  = threadIdx.x;
    const int lane = tid & 31;
    const int wid  = tid >> 5;
    const int wm   = wid >> 2;          // 0..1 : m-slice of 64
    const int wn   = wid & 3;           // 0..3 : n-slice of 32
    const int m0w  = wm * 64;
    const int n0w  = wn * 32;
    const int gid  = lane >> 2;         // 0..7
    const int tig  = lane & 3;          // 0..3

    const float* b1b = b1 + b * H_;
    const float* w2b = w2 + b * H_;

    // ---- per-lane ldmatrix offsets (within a stage), s=0 chunk pair ----
    const int lane15 = lane & 15;
    const int laneHi = lane >> 4;       // 0/1 -> k-chunk within k16 step
    uint32_t offAh[4], offAl[4], offBh[2], offBl[2];
#pragma unroll
    for (int mt = 0; mt < 4; ++mt) {
        const int row = m0w + mt * 16 + lane15;
        const uint32_t off = (uint32_t)row * 64u + (uint32_t)((laneHi ^ ((row >> 1) & 3)) * 16);
        offAh[mt] = OFF_AH + off;
        offAl[mt] = OFF_AL + off;
    }
#pragma unroll
    for (int np = 0; np < 2; ++np) {
        const int row = n0w + np * 16 + lane15;
        const uint32_t off = (uint32_t)row * 64u + (uint32_t)((laneHi ^ ((row >> 1) & 3)) * 16);
        offBh[np] = OFF_BH + off;
        offBl[np] = OFF_BL + off;
    }

    // ---- cp.async loader for one stage (tile index tt) ----
    auto load_stage = [&](int stg, int tt) {
        const int hc = tt >> 4;
        const int kg = (tt & 15) * 32;          // k offset in F
        const int h0p = hc * 128;
        const uint32_t sb = dyn + (uint32_t)stg * STAGE_BYTES;
        const int rr0 = tid >> 2;               // 0..63
        const int c   = tid & 3;                // 16B chunk
#pragma unroll
        for (int j = 0; j < 8; ++j) {
            const int op = j >> 1;              // 0=Ah 1=Al 2=Bh 3=Bl
            const int rr = rr0 + (j & 1) * 64;  // 0..127
            const uint32_t dst = sb + (uint32_t)op * 8192u + (uint32_t)rr * 64u
                               + (uint32_t)((c ^ ((rr >> 1) & 3)) * 16);
            const uint16_t* src;
            if (op == 0)      src = g_xh  + ((size_t)(t0 + rr) * B_ + b) * F_ + kg + c * 8;
            else if (op == 1) src = g_xl  + ((size_t)(t0 + rr) * B_ + b) * F_ + kg + c * 8;
            else if (op == 2) src = g_whT + ((size_t)b * H_ + h0p + rr) * F_ + kg + c * 8;
            else              src = g_wlT + ((size_t)b * H_ + h0p + rr) * F_ + kg + c * 8;
            cp16(dst, src);
        }
    };

    float acc[4][4][4];
#pragma unroll
    for (int mt = 0; mt < 4; ++mt)
#pragma unroll
        for (int nt = 0; nt < 4; ++nt)
#pragma unroll
            for (int c = 0; c < 4; ++c) acc[mt][nt][c] = 0.0f;

    float rowsum[8];
#pragma unroll
    for (int i = 0; i < 8; ++i) rowsum[i] = 0.0f;

    // ---- prologue: stages 0,1 in flight ----
    load_stage(0, 0);
    asm volatile("cp.async.commit_group;" ::: "memory");
    load_stage(1, 1);
    asm volatile("cp.async.commit_group;" ::: "memory");

    int sComp = 0, sLoad = 2;

    for (int tt = 0; tt < 128; ++tt) {
        asm volatile("cp.async.wait_group 1;" ::: "memory");
        __syncthreads();   // stage tt visible to all; all warps done with stage tt-1

        if (tt < 126) load_stage(sLoad, tt + 2);
        asm volatile("cp.async.commit_group;" ::: "memory");

        // ---- compute stage sComp: TK=32 = two k16 steps ----
        const uint32_t sb = dyn + (uint32_t)sComp * STAGE_BYTES;
#pragma unroll
        for (int s = 0; s < 2; ++s) {
            const uint32_t xs = s ? 32u : 0u;   // chunk-pair XOR (swizzle-compatible)
            uint32_t ah[4][4], al[4][4];
#pragma unroll
            for (int mt = 0; mt < 4; ++mt) {
                ldsm4(ah[mt], (sb + offAh[mt]) ^ xs);
                ldsm4(al[mt], (sb + offAl[mt]) ^ xs);
            }
#pragma unroll
            for (int np = 0; np < 2; ++np) {
                uint32_t bh[4], bl[4];
                ldsm4(bh, (sb + offBh[np]) ^ xs);
                ldsm4(bl, (sb + offBl[np]) ^ xs);
#pragma unroll
                for (int half = 0; half < 2; ++half) {
                    const int nt = np * 2 + half;
                    const uint32_t bh0 = bh[half], bh1 = bh[half + 2];
                    const uint32_t bl0 = bl[half], bl1 = bl[half + 2];
#pragma unroll
                    for (int mt = 0; mt < 4; ++mt) {
                        mma_bf16(acc[mt][nt], ah[mt][0], ah[mt][1], ah[mt][2], ah[mt][3], bh0, bh1);
                        mma_bf16(acc[mt][nt], ah[mt][0], ah[mt][1], ah[mt][2], ah[mt][3], bl0, bl1);
                        mma_bf16(acc[mt][nt], al[mt][0], al[mt][1], al[mt][2], al[mt][3], bh0, bh1);
                    }
                }
            }
        }

        // ---- end of H-chunk: fused relu(acc+b1)*w2 epilogue, re-zero acc ----
        if ((tt & 15) == 15) {
            const int hc = tt >> 4;
            const int h0 = hc * 128;
#pragma unroll
            for (int nt = 0; nt < 4; ++nt) {
                const int h = h0 + n0w + nt * 8 + tig * 2;
                const float bb0 = __ldg(b1b + h), bb1 = __ldg(b1b + h + 1);
                const float ww0 = __ldg(w2b + h), ww1 = __ldg(w2b + h + 1);
#pragma unroll
                for (int mt = 0; mt < 4; ++mt) {
                    rowsum[mt * 2]     += fmaxf(acc[mt][nt][0] + bb0, 0.f) * ww0
                                        + fmaxf(acc[mt][nt][1] + bb1, 0.f) * ww1;
                    rowsum[mt * 2 + 1] += fmaxf(acc[mt][nt][2] + bb0, 0.f) * ww0
                                        + fmaxf(acc[mt][nt][3] + bb1, 0.f) * ww1;
                }
            }
#pragma unroll
            for (int mt = 0; mt < 4; ++mt)
#pragma unroll
                for (int nt = 0; nt < 4; ++nt)
#pragma unroll
                    for (int c = 0; c < 4; ++c) acc[mt][nt][c] = 0.0f;
        }

        sComp = (sComp == 2) ? 0 : sComp + 1;
        sLoad = (sLoad == 2) ? 0 : sLoad + 1;
    }

    // ---- reduce over n: within warp (tig lanes), then across the 4 n-warps ----
#pragma unroll
    for (int i = 0; i < 8; ++i) {
        rowsum[i] += __shfl_xor_sync(0xffffffffu, rowsum[i], 1);
        rowsum[i] += __shfl_xor_sync(0xffffffffu, rowsum[i], 2);
    }

    if (tig == 0) {
#pragma unroll
        for (int mt = 0; mt < 4; ++mt) {
            red[(m0w + mt * 16 + gid) * 4 + wn]     = rowsum[mt * 2];
            red[(m0w + mt * 16 + gid + 8) * 4 + wn] = rowsum[mt * 2 + 1];
        }
    }
    __syncthreads();

    if (tid < 128) {
        const float s = red[tid * 4] + red[tid * 4 + 1] + red[tid * 4 + 2] + red[tid * 4 + 3] + b2[b];
        out[(size_t)(t0 + tid) * B_ + b] = s;
    }
}

// ---------------------------------------------------------------------------
extern "C" void kernel_launch(void* const* d_in, const int* in_sizes, int n_in,
                              void* d_out, int out_size)
{
    (void)in_sizes; (void)n_in; (void)out_size;
    const float* x  = (const float*)d_in[0];
    const float* w1 = (const float*)d_in[1];
    const float* b1 = (const float*)d_in[2];
    const float* w2 = (const float*)d_in[3];
    const float* b2 = (const float*)d_in[4];
    float* out = (float*)d_out;

    convert_x_kernel<<<X_ELEMS / (256 * 4), 256>>>(x);
    {
        dim3 g(F_ / 32, H_ / 32, B_);
        convert_wT_kernel<<<g, 256>>>(w1);
    }

    static int attr_done = 0;
    if (!attr_done) {
        cudaFuncSetAttribute(mothernet_mma2, cudaFuncAttributeMaxDynamicSharedMemorySize, DYN_BYTES);
        attr_done = 1;
    }
    dim3 grid(T_ / 128, B_);   // 32 x 8 = 256 CTAs, 2/SM -> one wave
    mothernet_mma2<<<grid, 256, DYN_BYTES>>>(b1, w2, b2, out);
}

// round 8
// speedup vs baseline: 1.0679x; 1.0679x over previous
#include <cuda_runtime.h>
#include <cuda_bf16.h>
#include <cstdint>

// Problem constants (fixed by the reference)
#define T_ 4096
#define B_ 8
#define F_ 512
#define H_ 1024

#define X_ELEMS (T_ * B_ * F_)    // 16,777,216
#define W_ELEMS (B_ * F_ * H_)    //  4,194,304

// bf16 hi/lo scratch (static device globals: the legal scratch mechanism)
// x kept [T,B,F] (k contiguous); w transposed to [B,H,F] (k contiguous)
__device__ uint16_t g_xh[X_ELEMS];
__device__ uint16_t g_xl[X_ELEMS];
__device__ uint16_t g_whT[W_ELEMS];
__device__ uint16_t g_wlT[W_ELEMS];

// ---------------------------------------------------------------------------
// helpers
// ---------------------------------------------------------------------------
__device__ __forceinline__ float fix_nan(float v) {
    unsigned u = __float_as_uint(v) & 0x7fffffffu;
    return (u > 0x7f800000u) ? 0.0f : v;
}
__device__ __forceinline__ float bfr(float v) {
    return __bfloat162float(__float2bfloat16(v));
}
__device__ __forceinline__ uint32_t f2bf2(float lo, float hi) {
    uint32_t r;
    asm("cvt.rn.bf16x2.f32 %0, %1, %2;" : "=r"(r) : "f"(hi), "f"(lo));
    return r;
}
__device__ __forceinline__ uint16_t f2bf1(float v) {
    __nv_bfloat16 h = __float2bfloat16(v);
    return *reinterpret_cast<uint16_t*>(&h);
}
__device__ __forceinline__ uint32_t smem_u32(const void* p) {
    uint32_t r;
    asm("{ .reg .u64 t; cvta.to.shared.u64 t, %1; cvt.u32.u64 %0, t; }" : "=r"(r) : "l"(p));
    return r;
}
__device__ __forceinline__ void cp16(uint32_t dst, const void* src) {
    asm volatile("cp.async.cg.shared.global [%0], [%1], 16;" :: "r"(dst), "l"(src) : "memory");
}
__device__ __forceinline__ void ldsm4(uint32_t r[4], uint32_t addr) {
    asm volatile("ldmatrix.sync.aligned.m8n8.x4.shared.b16 {%0,%1,%2,%3}, [%4];"
                 : "=r"(r[0]), "=r"(r[1]), "=r"(r[2]), "=r"(r[3]) : "r"(addr));
}
__device__ __forceinline__ void mma_bf16(float c[4],
                                         uint32_t a0, uint32_t a1, uint32_t a2, uint32_t a3,
                                         uint32_t b0, uint32_t b1) {
    asm volatile("mma.sync.aligned.m16n8k16.row.col.f32.bf16.bf16.f32 "
                 "{%0,%1,%2,%3}, {%4,%5,%6,%7}, {%8,%9}, {%0,%1,%2,%3};"
                 : "+f"(c[0]), "+f"(c[1]), "+f"(c[2]), "+f"(c[3])
                 : "r"(a0), "r"(a1), "r"(a2), "r"(a3), "r"(b0), "r"(b1));
}

// ---------------------------------------------------------------------------
// Pre-conversion kernels
// ---------------------------------------------------------------------------
__global__ void __launch_bounds__(256)
convert_x_kernel(const float* __restrict__ x)
{
    const size_t i = ((size_t)blockIdx.x * 256 + threadIdx.x) * 4;
    float4 v = *(const float4*)(x + i);
    float a = fix_nan(v.x), bb = fix_nan(v.y), c = fix_nan(v.z), d = fix_nan(v.w);
    float ha = bfr(a), hb = bfr(bb), hc = bfr(c), hd = bfr(d);
    *(uint2*)(g_xh + i) = make_uint2(f2bf2(ha, hb), f2bf2(hc, hd));
    *(uint2*)(g_xl + i) = make_uint2(f2bf2(a - ha, bb - hb), f2bf2(c - hc, d - hd));
}

// transpose w1 [B][F][H] -> [B][H][F], split into bf16 hi/lo
__global__ void __launch_bounds__(256)
convert_wT_kernel(const float* __restrict__ w1)
{
    __shared__ float tile[32][33];
    const int k0 = blockIdx.x * 32;
    const int n0 = blockIdx.y * 32;
    const int b  = blockIdx.z;
    const int tx = threadIdx.x & 31;
    const int ty = threadIdx.x >> 5;   // 0..7

#pragma unroll
    for (int r = 0; r < 4; ++r) {
        const int k = ty + 8 * r;
        tile[k][tx] = w1[((size_t)b * F_ + (k0 + k)) * H_ + n0 + tx];
    }
    __syncthreads();
#pragma unroll
    for (int r = 0; r < 4; ++r) {
        const int n = ty + 8 * r;
        const float v = tile[tx][n];          // out[n][k=tx] = in[k=tx][n]
        const float h = bfr(v);
        const size_t o = ((size_t)b * H_ + (n0 + n)) * F_ + k0 + tx;
        g_whT[o] = f2bf1(h);
        g_wlT[o] = f2bf1(v - h);
    }
}

// ---------------------------------------------------------------------------
// mma.sync GEMM, cp.async 3-stage pipeline, TK=32, flat (hc,kt) loop.
// 4 warps/CTA, warp tile 64m x 64n (acc[4][8][4]) -> 85 B smem per MMA.
// Stage layout (32 KB): Ah[128x64B] Al Bh Bl; 64B rows, XOR swizzle.
// ---------------------------------------------------------------------------
#define STAGE_BYTES 32768
#define OFF_AH 0
#define OFF_AL 8192
#define OFF_BH 16384
#define OFF_BL 24576
#define DYN_BYTES (3 * STAGE_BYTES)

__global__ void __launch_bounds__(128, 2)
mothernet_mma3(const float* __restrict__ b1,   // [B, H]
               const float* __restrict__ w2,   // [B, H]
               const float* __restrict__ b2,   // [B]
               float* __restrict__ out)        // [T, B]
{
    extern __shared__ __align__(128) uint8_t dynraw[];
    __shared__ float red[128 * 2];

    const uint32_t dyn = smem_u32(dynraw);

    const int b    = blockIdx.y;
    const int t0   = blockIdx.x * 128;
    const int tid  = threadIdx.x;
    const int lane = tid & 31;
    const int wid  = tid >> 5;          // 0..3
    const int wm   = wid >> 1;          // 0..1 : m-slice of 64
    const int wn   = wid & 1;           // 0..1 : n-slice of 64
    const int m0w  = wm * 64;
    const int n0w  = wn * 64;
    const int gid  = lane >> 2;         // 0..7
    const int tig  = lane & 3;          // 0..3

    const float* b1b = b1 + b * H_;
    const float* w2b = w2 + b * H_;

    // ---- per-lane ldmatrix offsets (within a stage), s=0 chunk pair ----
    const int lane15 = lane & 15;
    const int laneHi = lane >> 4;       // 0/1 -> k-chunk within k16 step
    uint32_t offAh[4], offAl[4], offBh[4], offBl[4];
#pragma unroll
    for (int mt = 0; mt < 4; ++mt) {
        const int row = m0w + mt * 16 + lane15;
        const uint32_t off = (uint32_t)row * 64u + (uint32_t)((laneHi ^ ((row >> 1) & 3)) * 16);
        offAh[mt] = OFF_AH + off;
        offAl[mt] = OFF_AL + off;
    }
#pragma unroll
    for (int np = 0; np < 4; ++np) {
        const int row = n0w + np * 16 + lane15;
        const uint32_t off = (uint32_t)row * 64u + (uint32_t)((laneHi ^ ((row >> 1) & 3)) * 16);
        offBh[np] = OFF_BH + off;
        offBl[np] = OFF_BL + off;
    }

    // ---- cp.async loader for one stage (tile index tt): 16 chunks/thread ----
    auto load_stage = [&](int stg, int tt) {
        const int hc = tt >> 4;
        const int kg = (tt & 15) * 32;          // k offset in F
        const int h0p = hc * 128;
        const uint32_t sb = dyn + (uint32_t)stg * STAGE_BYTES;
        const int rr0 = tid >> 2;               // 0..31
        const int c   = tid & 3;                // 16B chunk
#pragma unroll
        for (int j = 0; j < 16; ++j) {
            const int op = j >> 2;              // 0=Ah 1=Al 2=Bh 3=Bl
            const int rr = rr0 + (j & 3) * 32;  // 0..127
            const uint32_t dst = sb + (uint32_t)op * 8192u + (uint32_t)rr * 64u
                               + (uint32_t)((c ^ ((rr >> 1) & 3)) * 16);
            const uint16_t* src;
            if (op == 0)      src = g_xh  + ((size_t)(t0 + rr) * B_ + b) * F_ + kg + c * 8;
            else if (op == 1) src = g_xl  + ((size_t)(t0 + rr) * B_ + b) * F_ + kg + c * 8;
            else if (op == 2) src = g_whT + ((size_t)b * H_ + h0p + rr) * F_ + kg + c * 8;
            else              src = g_wlT + ((size_t)b * H_ + h0p + rr) * F_ + kg + c * 8;
            cp16(dst, src);
        }
    };

    float acc[4][8][4];
#pragma unroll
    for (int mt = 0; mt < 4; ++mt)
#pragma unroll
        for (int nt = 0; nt < 8; ++nt)
#pragma unroll
            for (int c = 0; c < 4; ++c) acc[mt][nt][c] = 0.0f;

    float rowsum[8];
#pragma unroll
    for (int i = 0; i < 8; ++i) rowsum[i] = 0.0f;

    // ---- prologue: stages 0,1 in flight ----
    load_stage(0, 0);
    asm volatile("cp.async.commit_group;" ::: "memory");
    load_stage(1, 1);
    asm volatile("cp.async.commit_group;" ::: "memory");

    int sComp = 0, sLoad = 2;

    for (int tt = 0; tt < 128; ++tt) {
        asm volatile("cp.async.wait_group 1;" ::: "memory");
        __syncthreads();   // stage tt visible; all warps done with the stage being refilled

        if (tt < 126) load_stage(sLoad, tt + 2);
        asm volatile("cp.async.commit_group;" ::: "memory");

        // ---- compute stage sComp: TK=32 = two k16 steps ----
        const uint32_t sb = dyn + (uint32_t)sComp * STAGE_BYTES;
#pragma unroll
        for (int s = 0; s < 2; ++s) {
            const uint32_t xs = s ? 32u : 0u;   // k16 select (swizzle-compatible XOR)
            uint32_t ah[4][4], al[4][4];
#pragma unroll
            for (int mt = 0; mt < 4; ++mt) {
                ldsm4(ah[mt], (sb + offAh[mt]) ^ xs);
                ldsm4(al[mt], (sb + offAl[mt]) ^ xs);
            }
#pragma unroll
            for (int np = 0; np < 4; ++np) {
                uint32_t bh[4], bl[4];
                ldsm4(bh, (sb + offBh[np]) ^ xs);
                ldsm4(bl, (sb + offBl[np]) ^ xs);
#pragma unroll
                for (int half = 0; half < 2; ++half) {
                    const int nt = np * 2 + half;
                    const uint32_t bh0 = bh[half], bh1 = bh[half + 2];
                    const uint32_t bl0 = bl[half], bl1 = bl[half + 2];
#pragma unroll
                    for (int mt = 0; mt < 4; ++mt) {
                        mma_bf16(acc[mt][nt], ah[mt][0], ah[mt][1], ah[mt][2], ah[mt][3], bh0, bh1);
                        mma_bf16(acc[mt][nt], ah[mt][0], ah[mt][1], ah[mt][2], ah[mt][3], bl0, bl1);
                        mma_bf16(acc[mt][nt], al[mt][0], al[mt][1], al[mt][2], al[mt][3], bh0, bh1);
                    }
                }
            }
        }

        // ---- end of H-chunk: fused relu(acc+b1)*w2 epilogue, re-zero acc ----
        if ((tt & 15) == 15) {
            const int hc = tt >> 4;
            const int h0 = hc * 128;
#pragma unroll
            for (int nt = 0; nt < 8; ++nt) {
                const int h = h0 + n0w + nt * 8 + tig * 2;
                const float bb0 = __ldg(b1b + h), bb1 = __ldg(b1b + h + 1);
                const float ww0 = __ldg(w2b + h), ww1 = __ldg(w2b + h + 1);
#pragma unroll
                for (int mt = 0; mt < 4; ++mt) {
                    rowsum[mt * 2]     += fmaxf(acc[mt][nt][0] + bb0, 0.f) * ww0
                                        + fmaxf(acc[mt][nt][1] + bb1, 0.f) * ww1;
                    rowsum[mt * 2 + 1] += fmaxf(acc[mt][nt][2] + bb0, 0.f) * ww0
                                        + fmaxf(acc[mt][nt][3] + bb1, 0.f) * ww1;
                }
            }
#pragma unroll
            for (int mt = 0; mt < 4; ++mt)
#pragma unroll
                for (int nt = 0; nt < 8; ++nt)
#pragma unroll
                    for (int c = 0; c < 4; ++c) acc[mt][nt][c] = 0.0f;
        }

        sComp = (sComp == 2) ? 0 : sComp + 1;
        sLoad = (sLoad == 2) ? 0 : sLoad + 1;
    }

    // ---- reduce over n: within warp (tig lanes), then across the 2 n-warps ----
#pragma unroll
    for (int i = 0; i < 8; ++i) {
        rowsum[i] += __shfl_xor_sync(0xffffffffu, rowsum[i], 1);
        rowsum[i] += __shfl_xor_sync(0xffffffffu, rowsum[i], 2);
    }

    if (tig == 0) {
#pragma unroll
        for (int mt = 0; mt < 4; ++mt) {
            red[(m0w + mt * 16 + gid) * 2 + wn]     = rowsum[mt * 2];
            red[(m0w + mt * 16 + gid + 8) * 2 + wn] = rowsum[mt * 2 + 1];
        }
    }
    __syncthreads();

    if (tid < 128) {
        const float s = red[tid * 2] + red[tid * 2 + 1] + b2[b];
        out[(size_t)(t0 + tid) * B_ + b] = s;
    }
}

// ---------------------------------------------------------------------------
extern "C" void kernel_launch(void* const* d_in, const int* in_sizes, int n_in,
                              void* d_out, int out_size)
{
    (void)in_sizes; (void)n_in; (void)out_size;
    const float* x  = (const float*)d_in[0];
    const float* w1 = (const float*)d_in[1];
    const float* b1 = (const float*)d_in[2];
    const float* w2 = (const float*)d_in[3];
    const float* b2 = (const float*)d_in[4];
    float* out = (float*)d_out;

    convert_x_kernel<<<X_ELEMS / (256 * 4), 256>>>(x);
    {
        dim3 g(F_ / 32, H_ / 32, B_);
        convert_wT_kernel<<<g, 256>>>(w1);
    }

    static int attr_done = 0;
    if (!attr_done) {
        cudaFuncSetAttribute(mothernet_mma3, cudaFuncAttributeMaxDynamicSharedMemorySize, DYN_BYTES);
        attr_done = 1;
    }
    dim3 grid(T_ / 128, B_);   // 32 x 8 = 256 CTAs, 2/SM -> one wave
    mothernet_mma3<<<grid, 128, DYN_BYTES>>>(b1, w2, b2, out);
}